// round 16
// baseline (speedup 1.0000x reference)
#include <cuda_runtime.h>
#include <cuda_bf16.h>
#include <cuda_fp16.h>
#include <cstdint>

#define BB 2
#define SS 2048
#define DD 512
#define LL 6
#define HH 8
#define FF 2048
#define VV 32000
#define ROWS (BB*SS)   // 4096

// fp32 residual stream scratch
__device__ float g_h [ROWS * DD];
__device__ float g_t [ROWS * DD];
// fp16 activation planes
__device__ __align__(16) __half g_hf [ROWS * DD];
__device__ __align__(16) __half g_qf [ROWS * 3*DD];
__device__ __align__(16) __half g_of [ROWS * DD];
__device__ __align__(16) __half g_ff [ROWS * FF];
__device__ __align__(16) __half g_tf [ROWS * DD];
// fp16 pre-transposed weights [N][K]
__device__ __align__(16) __half g_qkvT_f[LL * 3*DD * DD];
__device__ __align__(16) __half g_woT_f [LL * DD * DD];
__device__ __align__(16) __half g_w1T_f [LL * FF * DD];
__device__ __align__(16) __half g_w2T_f [LL * DD * FF];
__device__ __align__(16) __half g_outT_f[VV * DD];

extern __shared__ char dynsm[];

// ---------------------------------------------------------------------------
__device__ __forceinline__ uint32_t smem_u32(const void* p) {
    uint32_t a;
    asm("{ .reg .u64 t; cvta.to.shared.u64 t, %1; cvt.u32.u64 %0, t; }"
        : "=r"(a) : "l"(p));
    return a;
}
__device__ __forceinline__ void cpa16(uint32_t s, const void* g) {
    asm volatile("cp.async.cg.shared.global [%0], [%1], 16;" :: "r"(s), "l"(g));
}
__device__ __forceinline__ uint32_t packh2(float x0, float x1) {
    __half2 p = __float22half2_rn(make_float2(x0, x1));
    return *(uint32_t*)&p;
}
__device__ __forceinline__ void mma_f16(float* d, const uint32_t* a, const uint32_t* b) {
    asm volatile("mma.sync.aligned.m16n8k16.row.col.f32.f16.f16.f32 "
        "{%0,%1,%2,%3}, {%4,%5,%6,%7}, {%8,%9}, {%0,%1,%2,%3};"
        : "+f"(d[0]), "+f"(d[1]), "+f"(d[2]), "+f"(d[3])
        : "r"(a[0]), "r"(a[1]), "r"(a[2]), "r"(a[3]), "r"(b[0]), "r"(b[1]));
}
__device__ __forceinline__ void ldm4(uint32_t* r, uint32_t a) {
    asm volatile("ldmatrix.sync.aligned.m8n8.x4.shared.b16 {%0,%1,%2,%3}, [%4];"
        : "=r"(r[0]), "=r"(r[1]), "=r"(r[2]), "=r"(r[3]) : "r"(a));
}
__device__ __forceinline__ void ldm4t(uint32_t* r, uint32_t a) {
    asm volatile("ldmatrix.sync.aligned.m8n8.x4.trans.shared.b16 {%0,%1,%2,%3}, [%4];"
        : "=r"(r[0]), "=r"(r[1]), "=r"(r[2]), "=r"(r[3]) : "r"(a));
}

// ---------------------------------------------------------------------------
// Weight prep: W[K,N] fp32 -> WT [N,K] fp16 (transpose), per-matrix via z
// ---------------------------------------------------------------------------
__global__ void wprep16_k(const float* __restrict__ W, __half* __restrict__ o,
                          int K, int N)
{
    __shared__ float ts[32][33];
    long moff = (long)blockIdx.z * K * N;
    int kb = blockIdx.y * 32, nb = blockIdx.x * 32;
    int r = threadIdx.x >> 5, c = threadIdx.x & 31;
    #pragma unroll
    for (int i = 0; i < 4; i++)
        ts[r + i*8][c] = W[moff + (long)(kb + r + i*8) * N + nb + c];
    __syncthreads();
    #pragma unroll
    for (int i = 0; i < 4; i++) {
        int n = r + i*8;
        o[moff + (long)(nb + n) * K + kb + c] = __float2half_rn(ts[c][n]);
    }
}

// ---------------------------------------------------------------------------
// Embedding + PE -> fp32 h + fp16 plane
// ---------------------------------------------------------------------------
__global__ void embed_k(const int* __restrict__ x, const float* __restrict__ emb,
                        const float* __restrict__ pe, float* __restrict__ h,
                        uint32_t* __restrict__ of)
{
    int row = blockIdx.x, tid = threadIdx.x;
    int s   = row & (SS - 1);
    int tok = x[row];
    float4 ev = ((const float4*)(emb + (long)tok * DD))[tid];
    float4 pv = ((const float4*)(pe  + (long)s   * DD))[tid];
    float4 o;
    o.x = ev.x + pv.x; o.y = ev.y + pv.y; o.z = ev.z + pv.z; o.w = ev.w + pv.w;
    ((float4*)(h + (long)row * DD))[tid] = o;
    int wi = row * (DD/2) + tid * 2;
    of[wi]   = packh2(o.x, o.y);
    of[wi+1] = packh2(o.z, o.w);
}

// ---------------------------------------------------------------------------
// out = LayerNorm(x (+ res)) * g + b -> fp32 + fp16 plane
// ---------------------------------------------------------------------------
__global__ void add_ln_k(const float* __restrict__ x, const float* __restrict__ res,
                         const float* __restrict__ gg, const float* __restrict__ bb,
                         float* __restrict__ outF, uint32_t* __restrict__ outP)
{
    int row = blockIdx.x, tid = threadIdx.x;
    float4 v = ((const float4*)(x + (long)row * DD))[tid];
    if (res) {
        float4 rv = ((const float4*)(res + (long)row * DD))[tid];
        v.x += rv.x; v.y += rv.y; v.z += rv.z; v.w += rv.w;
    }
    float s  = v.x + v.y + v.z + v.w;
    float s2 = v.x*v.x + v.y*v.y + v.z*v.z + v.w*v.w;
    #pragma unroll
    for (int o = 16; o; o >>= 1) {
        s  += __shfl_xor_sync(0xffffffffu, s,  o);
        s2 += __shfl_xor_sync(0xffffffffu, s2, o);
    }
    __shared__ float ssum[4], ssq[4];
    int wid = tid >> 5;
    if ((tid & 31) == 0) { ssum[wid] = s; ssq[wid] = s2; }
    __syncthreads();
    s  = ssum[0] + ssum[1] + ssum[2] + ssum[3];
    s2 = ssq[0]  + ssq[1]  + ssq[2]  + ssq[3];
    float mean = s * (1.0f / DD);
    float var  = s2 * (1.0f / DD) - mean * mean;
    float inv  = rsqrtf(var + 1e-5f);
    float4 gv = ((const float4*)gg)[tid];
    float4 bv = ((const float4*)bb)[tid];
    float4 o;
    o.x = (v.x - mean) * inv * gv.x + bv.x;
    o.y = (v.y - mean) * inv * gv.y + bv.y;
    o.z = (v.z - mean) * inv * gv.z + bv.z;
    o.w = (v.w - mean) * inv * gv.w + bv.w;
    ((float4*)(outF + (long)row * DD))[tid] = o;
    int wi = row * (DD/2) + tid * 2;
    outP[wi]   = packh2(o.x, o.y);
    outP[wi+1] = packh2(o.z, o.w);
}

// ---------------------------------------------------------------------------
// fp16 1-term tensor GEMM, 128x128 tile (round-15 proven).
// ---------------------------------------------------------------------------
#define GSTR 20
#define GPL  (128*GSTR)
#define F16_SMEM (4*GPL*4)     // 40960 B

template<int RELU, int OUTMODE>
__global__ __launch_bounds__(256)
void gemm_f16(const __half* __restrict__ Ap, const __half* __restrict__ Bp,
              const float* __restrict__ bias,
              float* __restrict__ C, uint32_t* __restrict__ Cf,
              int M, int N, int K)
{
    uint32_t* sm = (uint32_t*)dynsm;
    const int tid = threadIdx.x, warp = tid >> 5, lane = tid & 31;
    const int g = lane >> 2, c = lane & 3;
    const int bm = blockIdx.x * 128, bn = blockIdx.y * 128;
    const int wm = (warp >> 2) * 64, wn = (warp & 3) * 32;
    const uint32_t sb = smem_u32(sm);
    const int T = K / 32;

    const int alr = lane & 15, alw = (lane >> 4) * 4;
    const int blr = (lane & 7) + ((lane >> 4) << 3);
    const int blw = ((lane >> 3) & 1) * 4;

    auto stage = [&](int t, int b) {
        #pragma unroll
        for (int i = 0; i < 2; i++) {
            int id = tid + 256 * i, row = id >> 2, cc = id & 3;
            uint32_t doff = (uint32_t)(row * GSTR + cc * 4) * 4;
            uint32_t dbase = sb + (uint32_t)(b * 2 * GPL) * 4 + doff;
            cpa16(dbase,         Ap + (long)(bm + row) * K + t * 32 + cc * 8);
            cpa16(dbase + GPL*4, Bp + (long)(bn + row) * K + t * 32 + cc * 8);
        }
        asm volatile("cp.async.commit_group;");
    };

    float acc[4][4][4] = {};

    stage(0, 0);

    for (int t = 0; t < T; t++) {
        asm volatile("cp.async.wait_group 0;");
        __syncthreads();
        if (t + 1 < T) stage(t + 1, (t + 1) & 1);

        const uint32_t bufb = sb + (uint32_t)((t & 1) * 2 * GPL) * 4;

        #pragma unroll
        for (int kk = 0; kk < 2; kk++) {
            uint32_t ah[4][4];
            #pragma unroll
            for (int mt = 0; mt < 4; mt++) {
                uint32_t ao = (uint32_t)((wm + mt*16 + alr) * GSTR + kk*8 + alw) * 4;
                ldm4(ah[mt], bufb + ao);
            }
            #pragma unroll
            for (int pr = 0; pr < 2; pr++) {
                uint32_t bh[4];
                uint32_t bo = (uint32_t)((wn + pr*16 + blr) * GSTR + kk*8 + blw) * 4;
                ldm4(bh, bufb + GPL*4 + bo);
                #pragma unroll
                for (int sub = 0; sub < 2; sub++) {
                    int nt = pr * 2 + sub;
                    #pragma unroll
                    for (int mt = 0; mt < 4; mt++)
                        mma_f16(acc[mt][nt], ah[mt], bh + 2*sub);
                }
            }
        }
    }

    #pragma unroll
    for (int mt = 0; mt < 4; mt++) {
        #pragma unroll
        for (int nt = 0; nt < 4; nt++) {
            int col = bn + wn + nt*8 + 2*c;
            float bx = 0.f, by = 0.f;
            if (bias) { bx = bias[col]; by = bias[col + 1]; }
            long r0 = bm + wm + mt*16 + g;
            float v0 = acc[mt][nt][0] + bx, v1 = acc[mt][nt][1] + by;
            float v2 = acc[mt][nt][2] + bx, v3 = acc[mt][nt][3] + by;
            if (RELU) {
                v0 = fmaxf(v0, 0.f); v1 = fmaxf(v1, 0.f);
                v2 = fmaxf(v2, 0.f); v3 = fmaxf(v3, 0.f);
            }
            if (OUTMODE == 0) {
                *(float2*)(C + r0 * N + col)       = make_float2(v0, v1);
                *(float2*)(C + (r0 + 8) * N + col) = make_float2(v2, v3);
            } else {
                Cf[(r0 * N + col) >> 1]       = packh2(v0, v1);
                Cf[((r0 + 8) * N + col) >> 1] = packh2(v2, v3);
            }
        }
    }
}

// ---------------------------------------------------------------------------
// fp16 GEMM, 128x64 tile for occupancy-starved N=512 GEMMs (Wo, FF2).
// 8 warps as 4x2, warp tile 32x32. fp32 output + bias.
// ---------------------------------------------------------------------------
#define N64_BPL (128*GSTR)                 // A plane words
#define N64_BUF ((128+64)*GSTR)            // words per buffer
#define N64_SMEM (2*N64_BUF*4)             // 30720 B

__global__ __launch_bounds__(256)
void gemm_f16_n64(const __half* __restrict__ Ap, const __half* __restrict__ Bp,
                  const float* __restrict__ bias, float* __restrict__ C,
                  int M, int N, int K)
{
    uint32_t* sm = (uint32_t*)dynsm;
    const int tid = threadIdx.x, warp = tid >> 5, lane = tid & 31;
    const int g = lane >> 2, c = lane & 3;
    const int bm = blockIdx.x * 128, bn = blockIdx.y * 64;
    const int wm = (warp >> 1) * 32, wn = (warp & 1) * 32;
    const uint32_t sb = smem_u32(sm);
    const int T = K / 32;

    const int alr = lane & 15, alw = (lane >> 4) * 4;
    const int blr = (lane & 7) + ((lane >> 4) << 3);
    const int blw = ((lane >> 3) & 1) * 4;

    auto stage = [&](int t, int b) {
        #pragma unroll
        for (int i = 0; i < 3; i++) {
            int id = tid + 256 * i;        // 0..767
            uint32_t dbase = sb + (uint32_t)(b * N64_BUF) * 4;
            if (id < 512) {
                int row = id >> 2, cc = id & 3;
                cpa16(dbase + (uint32_t)(row * GSTR + cc * 4) * 4,
                      Ap + (long)(bm + row) * K + t * 32 + cc * 8);
            } else {
                int id2 = id - 512;
                int row = id2 >> 2, cc = id2 & 3;
                cpa16(dbase + (uint32_t)(N64_BPL + row * GSTR + cc * 4) * 4,
                      Bp + (long)(bn + row) * K + t * 32 + cc * 8);
            }
        }
        asm volatile("cp.async.commit_group;");
    };

    float acc[2][4][4] = {};

    stage(0, 0);

    for (int t = 0; t < T; t++) {
        asm volatile("cp.async.wait_group 0;");
        __syncthreads();
        if (t + 1 < T) stage(t + 1, (t + 1) & 1);

        const uint32_t bufb = sb + (uint32_t)((t & 1) * N64_BUF) * 4;

        #pragma unroll
        for (int kk = 0; kk < 2; kk++) {
            uint32_t ah[2][4];
            #pragma unroll
            for (int mt = 0; mt < 2; mt++) {
                uint32_t ao = (uint32_t)((wm + mt*16 + alr) * GSTR + kk*8 + alw) * 4;
                ldm4(ah[mt], bufb + ao);
            }
            #pragma unroll
            for (int pr = 0; pr < 2; pr++) {
                uint32_t bh[4];
                uint32_t bo = (uint32_t)(N64_BPL + (wn + pr*16 + blr) * GSTR + kk*8 + blw) * 4;
                ldm4(bh, bufb + bo);
                #pragma unroll
                for (int sub = 0; sub < 2; sub++) {
                    int nt = pr * 2 + sub;
                    #pragma unroll
                    for (int mt = 0; mt < 2; mt++)
                        mma_f16(acc[mt][nt], ah[mt], bh + 2*sub);
                }
            }
        }
    }

    #pragma unroll
    for (int mt = 0; mt < 2; mt++) {
        #pragma unroll
        for (int nt = 0; nt < 4; nt++) {
            int col = bn + wn + nt*8 + 2*c;
            float bx = bias[col], by = bias[col + 1];
            long r0 = bm + wm + mt*16 + g;
            *(float2*)(C + r0 * N + col) =
                make_float2(acc[mt][nt][0] + bx, acc[mt][nt][1] + by);
            *(float2*)(C + (r0 + 8) * N + col) =
                make_float2(acc[mt][nt][2] + bx, acc[mt][nt][3] + by);
        }
    }
}

// ---------------------------------------------------------------------------
// fp16 1-term flash attention, double-buffered K/V.
// CTA = 128 q-rows x (head, batch), 8 warps x 16 rows. Output: fp16 plane.
// ---------------------------------------------------------------------------
#define ASTR 36
#define AQF 0
#define AKV (128*ASTR)          // 4608 words: start of KV buffers
#define KVS (2*64*ASTR)         // 4608 words per buffer (K plane + V plane)
#define ATTF_SMEM ((128*ASTR + 2*KVS)*4)   // 55296 B

__global__ __launch_bounds__(256)
void attn_f16(const __half* __restrict__ qf, uint32_t* __restrict__ of)
{
    uint32_t* sm = (uint32_t*)dynsm;
    const uint32_t sb = smem_u32(sm);
    const int tid = threadIdx.x, warp = tid >> 5, lane = tid & 31;
    const int g = lane >> 2, c = lane & 3;
    const int qt = (int)gridDim.x - 1 - (int)blockIdx.x;
    const int h = blockIdx.y, b = blockIdx.z;
    const long rowbase = (long)b * SS;
    const int qoff = h << 6;

    const int alr = lane & 15, alw = (lane >> 4) * 4;
    const int blr = (lane & 7) + ((lane >> 4) << 3);
    const int blw = ((lane >> 3) & 1) * 4;
    const int vlr = ((lane >> 3) & 1) * 8 + (lane & 7);
    const int vlw = (lane >> 4) * 4;

    auto stage_kv = [&](int kt, int bsel) {
        uint32_t kvb = AKV + bsel * KVS;
        #pragma unroll
        for (int i = 0; i < 4; i++) {
            int id = tid + 256 * i;
            int kv = id >> 9;                 // 0=K, 1=V
            int rem = id & 511;
            int row = rem >> 3, ch = rem & 7;
            uint32_t base = kvb + kv * (64*ASTR);
            cpa16(sb + (uint32_t)(base + row * ASTR + ch * 4) * 4,
                  qf + (rowbase + kt * 64 + row) * 1536 + (kv ? 1024 : 512) + qoff + ch * 8);
        }
        asm volatile("cp.async.commit_group;");
    };

    // stage Q
    #pragma unroll
    for (int i = 0; i < 4; i++) {
        int id = tid + 256 * i;
        int row = id >> 3, ch = id & 7;
        cpa16(sb + (uint32_t)(AQF + row * ASTR + ch * 4) * 4,
              qf + (rowbase + qt * 128 + row) * 1536 + qoff + ch * 8);
    }
    asm volatile("cp.async.commit_group;");
    asm volatile("cp.async.wait_group 0;");
    __syncthreads();

    uint32_t Qf[4][4];
    #pragma unroll
    for (int kk = 0; kk < 4; kk++) {
        uint32_t qo = (uint32_t)((warp*16 + alr) * ASTR + kk*8 + alw) * 4;
        ldm4(Qf[kk], sb + AQF*4 + qo);
    }

    float m0 = -1e30f, m1 = -1e30f, l0 = 0.f, l1 = 0.f;
    float O[8][4] = {};
    const int nk = 2 * qt + 2;
    const int rbase = qt * 128 + warp * 16;

    stage_kv(0, 0);

    for (int kt = 0; kt < nk; kt++) {
        if (kt + 1 < nk) {
            stage_kv(kt + 1, (kt + 1) & 1);
            asm volatile("cp.async.wait_group 1;");
        } else {
            asm volatile("cp.async.wait_group 0;");
        }
        __syncthreads();

        const uint32_t KFb = sb + (uint32_t)(AKV + (kt & 1) * KVS) * 4;
        const uint32_t VFb = KFb + (64*ASTR) * 4;

        // ---- S = Q K^T ----
        float sacc[8][4] = {};
        #pragma unroll
        for (int kk = 0; kk < 4; kk++) {
            #pragma unroll
            for (int pr = 0; pr < 4; pr++) {
                uint32_t bh[4];
                uint32_t bo = (uint32_t)((pr*16 + blr) * ASTR + kk*8 + blw) * 4;
                ldm4(bh, KFb + bo);
                #pragma unroll
                for (int sub = 0; sub < 2; sub++)
                    mma_f16(sacc[pr * 2 + sub], Qf[kk], bh + 2*sub);
            }
        }

        // ---- mask + online softmax ----
        const float scale = 0.125f;
        const bool diag = (kt >= 2 * qt);
        const int row0 = rbase + g, row1 = rbase + g + 8;
        const int colb = kt * 64 + 2 * c;
        float rm0 = -1e30f, rm1 = -1e30f;
        #pragma unroll
        for (int nt = 0; nt < 8; nt++) {
            int c0 = colb + nt * 8;
            float v0 = sacc[nt][0] * scale, v1 = sacc[nt][1] * scale;
            float v2 = sacc[nt][2] * scale, v3 = sacc[nt][3] * scale;
            if (diag) {
                if (c0     > row0) v0 = -1e30f;
                if (c0 + 1 > row0) v1 = -1e30f;
                if (c0     > row1) v2 = -1e30f;
                if (c0 + 1 > row1) v3 = -1e30f;
            }
            sacc[nt][0] = v0; sacc[nt][1] = v1; sacc[nt][2] = v2; sacc[nt][3] = v3;
            rm0 = fmaxf(rm0, fmaxf(v0, v1));
            rm1 = fmaxf(rm1, fmaxf(v2, v3));
        }
        #pragma unroll
        for (int o = 1; o < 4; o <<= 1) {
            rm0 = fmaxf(rm0, __shfl_xor_sync(0xffffffffu, rm0, o));
            rm1 = fmaxf(rm1, __shfl_xor_sync(0xffffffffu, rm1, o));
        }
        float nm0 = fmaxf(m0, rm0), nm1 = fmaxf(m1, rm1);
        float sf0 = __expf(m0 - nm0), sf1 = __expf(m1 - nm1);
        m0 = nm0; m1 = nm1;
        float rs0 = 0.f, rs1 = 0.f;
        #pragma unroll
        for (int nt = 0; nt < 8; nt++) {
            float p0 = __expf(sacc[nt][0] - nm0);
            float p1 = __expf(sacc[nt][1] - nm0);
            float p2 = __expf(sacc[nt][2] - nm1);
            float p3 = __expf(sacc[nt][3] - nm1);
            sacc[nt][0] = p0; sacc[nt][1] = p1; sacc[nt][2] = p2; sacc[nt][3] = p3;
            rs0 += p0 + p1; rs1 += p2 + p3;
        }
        #pragma unroll
        for (int o = 1; o < 4; o <<= 1) {
            rs0 += __shfl_xor_sync(0xffffffffu, rs0, o);
            rs1 += __shfl_xor_sync(0xffffffffu, rs1, o);
        }
        l0 = l0 * sf0 + rs0;
        l1 = l1 * sf1 + rs1;
        #pragma unroll
        for (int nt = 0; nt < 8; nt++) {
            O[nt][0] *= sf0; O[nt][1] *= sf0;
            O[nt][2] *= sf1; O[nt][3] *= sf1;
        }

        // ---- O += P V ----
        #pragma unroll
        for (int kk = 0; kk < 4; kk++) {
            uint32_t ah[4];
            ah[0] = packh2(sacc[2*kk][0],   sacc[2*kk][1]);
            ah[1] = packh2(sacc[2*kk][2],   sacc[2*kk][3]);
            ah[2] = packh2(sacc[2*kk+1][0], sacc[2*kk+1][1]);
            ah[3] = packh2(sacc[2*kk+1][2], sacc[2*kk+1][3]);
            #pragma unroll
            for (int pr = 0; pr < 4; pr++) {
                uint32_t bh[4];
                uint32_t vo = (uint32_t)((kk*16 + vlr) * ASTR + pr*8 + vlw) * 4;
                ldm4t(bh, VFb + vo);
                #pragma unroll
                for (int sub = 0; sub < 2; sub++)
                    mma_f16(O[pr * 2 + sub], ah, bh + 2*sub);
            }
        }
        __syncthreads();
    }

    float inv0 = 1.0f / l0, inv1 = 1.0f / l1;
    long grow0 = rowbase + rbase + g;
    #pragma unroll
    for (int nt = 0; nt < 8; nt++) {
        int col = qoff + nt * 8 + 2 * c;
        of[(grow0 * DD + col) >> 1]       = packh2(O[nt][0] * inv0, O[nt][1] * inv0);
        of[((grow0 + 8) * DD + col) >> 1] = packh2(O[nt][2] * inv1, O[nt][3] * inv1);
    }
}

// ---------------------------------------------------------------------------
extern "C" void kernel_launch(void* const* d_in, const int* in_sizes, int n_in,
                              void* d_out, int out_size)
{
    const int*   x    = (const int*)  d_in[0];
    const float* emb  = (const float*)d_in[1];
    const float* pe   = (const float*)d_in[2];
    const float* Wqkv = (const float*)d_in[3];
    const float* Wo   = (const float*)d_in[4];
    const float* bo   = (const float*)d_in[5];
    const float* g1   = (const float*)d_in[6];
    const float* b1   = (const float*)d_in[7];
    const float* g2   = (const float*)d_in[8];
    const float* b2   = (const float*)d_in[9];
    const float* W1   = (const float*)d_in[10];
    const float* bf1  = (const float*)d_in[11];
    const float* W2   = (const float*)d_in[12];
    const float* bf2  = (const float*)d_in[13];
    const float* gf   = (const float*)d_in[14];
    const float* bfp  = (const float*)d_in[15];
    const float* Wout = (const float*)d_in[16];
    const float* bfc  = (const float*)d_in[17];
    float* out = (float*)d_out;

    float *h, *t;
    cudaGetSymbolAddress((void**)&h, g_h);
    cudaGetSymbolAddress((void**)&t, g_t);
    __half *hf, *qf, *of, *ff, *tf;
    cudaGetSymbolAddress((void**)&hf, g_hf);
    cudaGetSymbolAddress((void**)&qf, g_qf);
    cudaGetSymbolAddress((void**)&of, g_of);
    cudaGetSymbolAddress((void**)&ff, g_ff);
    cudaGetSymbolAddress((void**)&tf, g_tf);
    __half *qkvTf, *woTf, *w1Tf, *w2Tf, *outTf;
    cudaGetSymbolAddress((void**)&qkvTf, g_qkvT_f);
    cudaGetSymbolAddress((void**)&woTf,  g_woT_f);
    cudaGetSymbolAddress((void**)&w1Tf,  g_w1T_f);
    cudaGetSymbolAddress((void**)&w2Tf,  g_w2T_f);
    cudaGetSymbolAddress((void**)&outTf, g_outT_f);

    cudaFuncSetAttribute(attn_f16, cudaFuncAttributeMaxDynamicSharedMemorySize, ATTF_SMEM);
    cudaFuncSetAttribute(gemm_f16<0,0>, cudaFuncAttributeMaxDynamicSharedMemorySize, F16_SMEM);
    cudaFuncSetAttribute(gemm_f16<0,1>, cudaFuncAttributeMaxDynamicSharedMemorySize, F16_SMEM);
    cudaFuncSetAttribute(gemm_f16<1,1>, cudaFuncAttributeMaxDynamicSharedMemorySize, F16_SMEM);
    cudaFuncSetAttribute(gemm_f16_n64, cudaFuncAttributeMaxDynamicSharedMemorySize, N64_SMEM);

    wprep16_k<<<dim3(3*DD/32, DD/32, LL), 256>>>(Wqkv, qkvTf, DD, 3*DD);
    wprep16_k<<<dim3(DD/32,   DD/32, LL), 256>>>(Wo,   woTf,  DD, DD);
    wprep16_k<<<dim3(FF/32,   DD/32, LL), 256>>>(W1,   w1Tf,  DD, FF);
    wprep16_k<<<dim3(DD/32,   FF/32, LL), 256>>>(W2,   w2Tf,  FF, DD);
    wprep16_k<<<dim3(VV/32,   DD/32, 1 ), 256>>>(Wout, outTf, DD, VV);

    embed_k<<<ROWS, 128>>>(x, emb, pe, h, (uint32_t*)hf);

    for (int l = 0; l < LL; l++) {
        // QKV -> fp16 plane
        gemm_f16<0,1><<<dim3(32, 12), 256, F16_SMEM>>>(
            hf, qkvTf + (long)l * 3*DD*DD, nullptr,
            nullptr, (uint32_t*)qf, ROWS, 3*DD, DD);
        // attention (double-buffered KV) -> fp16 plane
        attn_f16<<<dim3(SS/128, HH, BB), 256, ATTF_SMEM>>>(qf, (uint32_t*)of);
        // Wo (128x64 tiles, 256 CTAs) -> fp32 t
        gemm_f16_n64<<<dim3(32, 8), 256, N64_SMEM>>>(
            of, woTf + (long)l * DD*DD, bo + l * DD, t, ROWS, DD, DD);
        add_ln_k<<<ROWS, 128>>>(t, h, g1 + l * DD, b1 + l * DD, h, (uint32_t*)hf);
        // FF1 + relu -> fp16 plane
        gemm_f16<1,1><<<dim3(32, 16), 256, F16_SMEM>>>(
            hf, w1Tf + (long)l * FF*DD, bf1 + l * FF,
            nullptr, (uint32_t*)ff, ROWS, FF, DD);
        // FF2 (128x64 tiles, 256 CTAs) -> fp32 t
        gemm_f16_n64<<<dim3(32, 8), 256, N64_SMEM>>>(
            ff, w2Tf + (long)l * DD*FF, bf2 + l * DD, t, ROWS, DD, FF);
        add_ln_k<<<ROWS, 128>>>(t, h, g2 + l * DD, b2 + l * DD, h, (uint32_t*)hf);
    }

    add_ln_k<<<ROWS, 128>>>(h, nullptr, gf, bfp, t, (uint32_t*)tf);
    gemm_f16<0,0><<<dim3(32, 250), 256, F16_SMEM>>>(
        tf, outTf, bfc, out, nullptr, ROWS, VV, DD);
}

// round 17
// speedup vs baseline: 1.3967x; 1.3967x over previous
#include <cuda_runtime.h>
#include <cuda_bf16.h>
#include <cuda_fp16.h>
#include <cstdint>

#define BB 2
#define SS 2048
#define DD 512
#define LL 6
#define HH 8
#define FF 2048
#define VV 32000
#define ROWS (BB*SS)   // 4096

// fp32 residual stream scratch
__device__ float g_h [ROWS * DD];
__device__ float g_t [ROWS * DD];
// fp16 activation planes
__device__ __align__(16) __half g_hf [ROWS * DD];
__device__ __align__(16) __half g_qf [ROWS * 3*DD];
__device__ __align__(16) __half g_of [ROWS * DD];
__device__ __align__(16) __half g_ff [ROWS * FF];
__device__ __align__(16) __half g_tf [ROWS * DD];
// fp16 pre-transposed weights [N][K]
__device__ __align__(16) __half g_qkvT_f[LL * 3*DD * DD];
__device__ __align__(16) __half g_woT_f [LL * DD * DD];
__device__ __align__(16) __half g_w1T_f [LL * FF * DD];
__device__ __align__(16) __half g_w2T_f [LL * DD * FF];
__device__ __align__(16) __half g_outT_f[VV * DD];

extern __shared__ char dynsm[];

// ---------------------------------------------------------------------------
__device__ __forceinline__ uint32_t smem_u32(const void* p) {
    uint32_t a;
    asm("{ .reg .u64 t; cvta.to.shared.u64 t, %1; cvt.u32.u64 %0, t; }"
        : "=r"(a) : "l"(p));
    return a;
}
__device__ __forceinline__ void cpa16(uint32_t s, const void* g) {
    asm volatile("cp.async.cg.shared.global [%0], [%1], 16;" :: "r"(s), "l"(g));
}
__device__ __forceinline__ uint32_t packh2(float x0, float x1) {
    __half2 p = __float22half2_rn(make_float2(x0, x1));
    return *(uint32_t*)&p;
}
__device__ __forceinline__ void mma_f16(float* d, const uint32_t* a, const uint32_t* b) {
    asm volatile("mma.sync.aligned.m16n8k16.row.col.f32.f16.f16.f32 "
        "{%0,%1,%2,%3}, {%4,%5,%6,%7}, {%8,%9}, {%0,%1,%2,%3};"
        : "+f"(d[0]), "+f"(d[1]), "+f"(d[2]), "+f"(d[3])
        : "r"(a[0]), "r"(a[1]), "r"(a[2]), "r"(a[3]), "r"(b[0]), "r"(b[1]));
}
__device__ __forceinline__ void ldm4(uint32_t* r, uint32_t a) {
    asm volatile("ldmatrix.sync.aligned.m8n8.x4.shared.b16 {%0,%1,%2,%3}, [%4];"
        : "=r"(r[0]), "=r"(r[1]), "=r"(r[2]), "=r"(r[3]) : "r"(a));
}
__device__ __forceinline__ void ldm4t(uint32_t* r, uint32_t a) {
    asm volatile("ldmatrix.sync.aligned.m8n8.x4.trans.shared.b16 {%0,%1,%2,%3}, [%4];"
        : "=r"(r[0]), "=r"(r[1]), "=r"(r[2]), "=r"(r[3]) : "r"(a));
}

// ---------------------------------------------------------------------------
// Weight prep: W[K,N] fp32 -> WT [N,K] fp16 (transpose), per-matrix via z
// ---------------------------------------------------------------------------
__global__ void wprep16_k(const float* __restrict__ W, __half* __restrict__ o,
                          int K, int N)
{
    __shared__ float ts[32][33];
    long moff = (long)blockIdx.z * K * N;
    int kb = blockIdx.y * 32, nb = blockIdx.x * 32;
    int r = threadIdx.x >> 5, c = threadIdx.x & 31;
    #pragma unroll
    for (int i = 0; i < 4; i++)
        ts[r + i*8][c] = W[moff + (long)(kb + r + i*8) * N + nb + c];
    __syncthreads();
    #pragma unroll
    for (int i = 0; i < 4; i++) {
        int n = r + i*8;
        o[moff + (long)(nb + n) * K + kb + c] = __float2half_rn(ts[c][n]);
    }
}

// ---------------------------------------------------------------------------
// Embedding + PE -> fp32 h + fp16 plane
// ---------------------------------------------------------------------------
__global__ void embed_k(const int* __restrict__ x, const float* __restrict__ emb,
                        const float* __restrict__ pe, float* __restrict__ h,
                        uint32_t* __restrict__ of)
{
    int row = blockIdx.x, tid = threadIdx.x;
    int s   = row & (SS - 1);
    int tok = x[row];
    float4 ev = ((const float4*)(emb + (long)tok * DD))[tid];
    float4 pv = ((const float4*)(pe  + (long)s   * DD))[tid];
    float4 o;
    o.x = ev.x + pv.x; o.y = ev.y + pv.y; o.z = ev.z + pv.z; o.w = ev.w + pv.w;
    ((float4*)(h + (long)row * DD))[tid] = o;
    int wi = row * (DD/2) + tid * 2;
    of[wi]   = packh2(o.x, o.y);
    of[wi+1] = packh2(o.z, o.w);
}

// ---------------------------------------------------------------------------
// out = LayerNorm(x (+ res)) * g + b -> fp32 + fp16 plane
// ---------------------------------------------------------------------------
__global__ void add_ln_k(const float* __restrict__ x, const float* __restrict__ res,
                         const float* __restrict__ gg, const float* __restrict__ bb,
                         float* __restrict__ outF, uint32_t* __restrict__ outP)
{
    int row = blockIdx.x, tid = threadIdx.x;
    float4 v = ((const float4*)(x + (long)row * DD))[tid];
    if (res) {
        float4 rv = ((const float4*)(res + (long)row * DD))[tid];
        v.x += rv.x; v.y += rv.y; v.z += rv.z; v.w += rv.w;
    }
    float s  = v.x + v.y + v.z + v.w;
    float s2 = v.x*v.x + v.y*v.y + v.z*v.z + v.w*v.w;
    #pragma unroll
    for (int o = 16; o; o >>= 1) {
        s  += __shfl_xor_sync(0xffffffffu, s,  o);
        s2 += __shfl_xor_sync(0xffffffffu, s2, o);
    }
    __shared__ float ssum[4], ssq[4];
    int wid = tid >> 5;
    if ((tid & 31) == 0) { ssum[wid] = s; ssq[wid] = s2; }
    __syncthreads();
    s  = ssum[0] + ssum[1] + ssum[2] + ssum[3];
    s2 = ssq[0]  + ssq[1]  + ssq[2]  + ssq[3];
    float mean = s * (1.0f / DD);
    float var  = s2 * (1.0f / DD) - mean * mean;
    float inv  = rsqrtf(var + 1e-5f);
    float4 gv = ((const float4*)gg)[tid];
    float4 bv = ((const float4*)bb)[tid];
    float4 o;
    o.x = (v.x - mean) * inv * gv.x + bv.x;
    o.y = (v.y - mean) * inv * gv.y + bv.y;
    o.z = (v.z - mean) * inv * gv.z + bv.z;
    o.w = (v.w - mean) * inv * gv.w + bv.w;
    ((float4*)(outF + (long)row * DD))[tid] = o;
    int wi = row * (DD/2) + tid * 2;
    outP[wi]   = packh2(o.x, o.y);
    outP[wi+1] = packh2(o.z, o.w);
}

// ---------------------------------------------------------------------------
// fp16 1-term tensor GEMM, 128x128 tile (round-15 proven).
// ---------------------------------------------------------------------------
#define GSTR 20
#define GPL  (128*GSTR)
#define F16_SMEM (4*GPL*4)     // 40960 B

template<int RELU, int OUTMODE>
__global__ __launch_bounds__(256)
void gemm_f16(const __half* __restrict__ Ap, const __half* __restrict__ Bp,
              const float* __restrict__ bias,
              float* __restrict__ C, uint32_t* __restrict__ Cf,
              int M, int N, int K)
{
    uint32_t* sm = (uint32_t*)dynsm;
    const int tid = threadIdx.x, warp = tid >> 5, lane = tid & 31;
    const int g = lane >> 2, c = lane & 3;
    const int bm = blockIdx.x * 128, bn = blockIdx.y * 128;
    const int wm = (warp >> 2) * 64, wn = (warp & 3) * 32;
    const uint32_t sb = smem_u32(sm);
    const int T = K / 32;

    const int alr = lane & 15, alw = (lane >> 4) * 4;
    const int blr = (lane & 7) + ((lane >> 4) << 3);
    const int blw = ((lane >> 3) & 1) * 4;

    auto stage = [&](int t, int b) {
        #pragma unroll
        for (int i = 0; i < 2; i++) {
            int id = tid + 256 * i, row = id >> 2, cc = id & 3;
            uint32_t doff = (uint32_t)(row * GSTR + cc * 4) * 4;
            uint32_t dbase = sb + (uint32_t)(b * 2 * GPL) * 4 + doff;
            cpa16(dbase,         Ap + (long)(bm + row) * K + t * 32 + cc * 8);
            cpa16(dbase + GPL*4, Bp + (long)(bn + row) * K + t * 32 + cc * 8);
        }
        asm volatile("cp.async.commit_group;");
    };

    float acc[4][4][4] = {};

    stage(0, 0);

    for (int t = 0; t < T; t++) {
        asm volatile("cp.async.wait_group 0;");
        __syncthreads();
        if (t + 1 < T) stage(t + 1, (t + 1) & 1);

        const uint32_t bufb = sb + (uint32_t)((t & 1) * 2 * GPL) * 4;

        #pragma unroll
        for (int kk = 0; kk < 2; kk++) {
            uint32_t ah[4][4];
            #pragma unroll
            for (int mt = 0; mt < 4; mt++) {
                uint32_t ao = (uint32_t)((wm + mt*16 + alr) * GSTR + kk*8 + alw) * 4;
                ldm4(ah[mt], bufb + ao);
            }
            #pragma unroll
            for (int pr = 0; pr < 2; pr++) {
                uint32_t bh[4];
                uint32_t bo = (uint32_t)((wn + pr*16 + blr) * GSTR + kk*8 + blw) * 4;
                ldm4(bh, bufb + GPL*4 + bo);
                #pragma unroll
                for (int sub = 0; sub < 2; sub++) {
                    int nt = pr * 2 + sub;
                    #pragma unroll
                    for (int mt = 0; mt < 4; mt++)
                        mma_f16(acc[mt][nt], ah[mt], bh + 2*sub);
                }
            }
        }
    }

    #pragma unroll
    for (int mt = 0; mt < 4; mt++) {
        #pragma unroll
        for (int nt = 0; nt < 4; nt++) {
            int col = bn + wn + nt*8 + 2*c;
            float bx = 0.f, by = 0.f;
            if (bias) { bx = bias[col]; by = bias[col + 1]; }
            long r0 = bm + wm + mt*16 + g;
            float v0 = acc[mt][nt][0] + bx, v1 = acc[mt][nt][1] + by;
            float v2 = acc[mt][nt][2] + bx, v3 = acc[mt][nt][3] + by;
            if (RELU) {
                v0 = fmaxf(v0, 0.f); v1 = fmaxf(v1, 0.f);
                v2 = fmaxf(v2, 0.f); v3 = fmaxf(v3, 0.f);
            }
            if (OUTMODE == 0) {
                *(float2*)(C + r0 * N + col)       = make_float2(v0, v1);
                *(float2*)(C + (r0 + 8) * N + col) = make_float2(v2, v3);
            } else {
                Cf[(r0 * N + col) >> 1]       = packh2(v0, v1);
                Cf[((r0 + 8) * N + col) >> 1] = packh2(v2, v3);
            }
        }
    }
}

// ---------------------------------------------------------------------------
// fp16 1-term flash attention, double-buffered K/V staging.
// CTA = 128 q-rows x (head, batch), 8 warps x 16 rows. Output: fp16 plane.
// ---------------------------------------------------------------------------
#define ASTR 36
#define AQF 0
#define AKV (128*ASTR)          // start of KV buffers (words)
#define KVS (2*64*ASTR)         // words per buffer (K plane + V plane)
#define ATTF_SMEM ((128*ASTR + 2*KVS)*4)   // 55296 B

__global__ __launch_bounds__(256)
void attn_f16(const __half* __restrict__ qf, uint32_t* __restrict__ of)
{
    uint32_t* sm = (uint32_t*)dynsm;
    const uint32_t sb = smem_u32(sm);
    const int tid = threadIdx.x, warp = tid >> 5, lane = tid & 31;
    const int g = lane >> 2, c = lane & 3;
    const int qt = (int)gridDim.x - 1 - (int)blockIdx.x;
    const int h = blockIdx.y, b = blockIdx.z;
    const long rowbase = (long)b * SS;
    const int qoff = h << 6;

    const int alr = lane & 15, alw = (lane >> 4) * 4;
    const int blr = (lane & 7) + ((lane >> 4) << 3);
    const int blw = ((lane >> 3) & 1) * 4;
    const int vlr = ((lane >> 3) & 1) * 8 + (lane & 7);
    const int vlw = (lane >> 4) * 4;

    auto stage_kv = [&](int kt, int bsel) {
        uint32_t kvb = AKV + bsel * KVS;
        #pragma unroll
        for (int i = 0; i < 4; i++) {
            int id = tid + 256 * i;
            int kv = id >> 9;
            int rem = id & 511;
            int row = rem >> 3, ch = rem & 7;
            uint32_t base = kvb + kv * (64*ASTR);
            cpa16(sb + (uint32_t)(base + row * ASTR + ch * 4) * 4,
                  qf + (rowbase + kt * 64 + row) * 1536 + (kv ? 1024 : 512) + qoff + ch * 8);
        }
        asm volatile("cp.async.commit_group;");
    };

    // stage Q
    #pragma unroll
    for (int i = 0; i < 4; i++) {
        int id = tid + 256 * i;
        int row = id >> 3, ch = id & 7;
        cpa16(sb + (uint32_t)(AQF + row * ASTR + ch * 4) * 4,
              qf + (rowbase + qt * 128 + row) * 1536 + qoff + ch * 8);
    }
    asm volatile("cp.async.commit_group;");
    asm volatile("cp.async.wait_group 0;");
    __syncthreads();

    uint32_t Qf[4][4];
    #pragma unroll
    for (int kk = 0; kk < 4; kk++) {
        uint32_t qo = (uint32_t)((warp*16 + alr) * ASTR + kk*8 + alw) * 4;
        ldm4(Qf[kk], sb + AQF*4 + qo);
    }

    float m0 = -1e30f, m1 = -1e30f, l0 = 0.f, l1 = 0.f;
    float O[8][4] = {};
    const int nk = 2 * qt + 2;
    const int rbase = qt * 128 + warp * 16;

    stage_kv(0, 0);

    for (int kt = 0; kt < nk; kt++) {
        if (kt + 1 < nk) {
            stage_kv(kt + 1, (kt + 1) & 1);
            asm volatile("cp.async.wait_group 1;");
        } else {
            asm volatile("cp.async.wait_group 0;");
        }
        __syncthreads();

        const uint32_t KFb = sb + (uint32_t)(AKV + (kt & 1) * KVS) * 4;
        const uint32_t VFb = KFb + (64*ASTR) * 4;

        // ---- S = Q K^T ----
        float sacc[8][4] = {};
        #pragma unroll
        for (int kk = 0; kk < 4; kk++) {
            #pragma unroll
            for (int pr = 0; pr < 4; pr++) {
                uint32_t bh[4];
                uint32_t bo = (uint32_t)((pr*16 + blr) * ASTR + kk*8 + blw) * 4;
                ldm4(bh, KFb + bo);
                #pragma unroll
                for (int sub = 0; sub < 2; sub++)
                    mma_f16(sacc[pr * 2 + sub], Qf[kk], bh + 2*sub);
            }
        }

        // ---- mask + online softmax ----
        const float scale = 0.125f;
        const bool diag = (kt >= 2 * qt);
        const int row0 = rbase + g, row1 = rbase + g + 8;
        const int colb = kt * 64 + 2 * c;
        float rm0 = -1e30f, rm1 = -1e30f;
        #pragma unroll
        for (int nt = 0; nt < 8; nt++) {
            int c0 = colb + nt * 8;
            float v0 = sacc[nt][0] * scale, v1 = sacc[nt][1] * scale;
            float v2 = sacc[nt][2] * scale, v3 = sacc[nt][3] * scale;
            if (diag) {
                if (c0     > row0) v0 = -1e30f;
                if (c0 + 1 > row0) v1 = -1e30f;
                if (c0     > row1) v2 = -1e30f;
                if (c0 + 1 > row1) v3 = -1e30f;
            }
            sacc[nt][0] = v0; sacc[nt][1] = v1; sacc[nt][2] = v2; sacc[nt][3] = v3;
            rm0 = fmaxf(rm0, fmaxf(v0, v1));
            rm1 = fmaxf(rm1, fmaxf(v2, v3));
        }
        #pragma unroll
        for (int o = 1; o < 4; o <<= 1) {
            rm0 = fmaxf(rm0, __shfl_xor_sync(0xffffffffu, rm0, o));
            rm1 = fmaxf(rm1, __shfl_xor_sync(0xffffffffu, rm1, o));
        }
        float nm0 = fmaxf(m0, rm0), nm1 = fmaxf(m1, rm1);
        float sf0 = __expf(m0 - nm0), sf1 = __expf(m1 - nm1);
        m0 = nm0; m1 = nm1;
        float rs0 = 0.f, rs1 = 0.f;
        #pragma unroll
        for (int nt = 0; nt < 8; nt++) {
            float p0 = __expf(sacc[nt][0] - nm0);
            float p1 = __expf(sacc[nt][1] - nm0);
            float p2 = __expf(sacc[nt][2] - nm1);
            float p3 = __expf(sacc[nt][3] - nm1);
            sacc[nt][0] = p0; sacc[nt][1] = p1; sacc[nt][2] = p2; sacc[nt][3] = p3;
            rs0 += p0 + p1; rs1 += p2 + p3;
        }
        #pragma unroll
        for (int o = 1; o < 4; o <<= 1) {
            rs0 += __shfl_xor_sync(0xffffffffu, rs0, o);
            rs1 += __shfl_xor_sync(0xffffffffu, rs1, o);
        }
        l0 = l0 * sf0 + rs0;
        l1 = l1 * sf1 + rs1;
        #pragma unroll
        for (int nt = 0; nt < 8; nt++) {
            O[nt][0] *= sf0; O[nt][1] *= sf0;
            O[nt][2] *= sf1; O[nt][3] *= sf1;
        }

        // ---- O += P V ----
        #pragma unroll
        for (int kk = 0; kk < 4; kk++) {
            uint32_t ah[4];
            ah[0] = packh2(sacc[2*kk][0],   sacc[2*kk][1]);
            ah[1] = packh2(sacc[2*kk][2],   sacc[2*kk][3]);
            ah[2] = packh2(sacc[2*kk+1][0], sacc[2*kk+1][1]);
            ah[3] = packh2(sacc[2*kk+1][2], sacc[2*kk+1][3]);
            #pragma unroll
            for (int pr = 0; pr < 4; pr++) {
                uint32_t bh[4];
                uint32_t vo = (uint32_t)((kk*16 + vlr) * ASTR + pr*8 + vlw) * 4;
                ldm4t(bh, VFb + vo);
                #pragma unroll
                for (int sub = 0; sub < 2; sub++)
                    mma_f16(O[pr * 2 + sub], ah, bh + 2*sub);
            }
        }
        __syncthreads();
    }

    float inv0 = 1.0f / l0, inv1 = 1.0f / l1;
    long grow0 = rowbase + rbase + g;
    #pragma unroll
    for (int nt = 0; nt < 8; nt++) {
        int col = qoff + nt * 8 + 2 * c;
        of[(grow0 * DD + col) >> 1]       = packh2(O[nt][0] * inv0, O[nt][1] * inv0);
        of[((grow0 + 8) * DD + col) >> 1] = packh2(O[nt][2] * inv1, O[nt][3] * inv1);
    }
}

// ---------------------------------------------------------------------------
extern "C" void kernel_launch(void* const* d_in, const int* in_sizes, int n_in,
                              void* d_out, int out_size)
{
    const int*   x    = (const int*)  d_in[0];
    const float* emb  = (const float*)d_in[1];
    const float* pe   = (const float*)d_in[2];
    const float* Wqkv = (const float*)d_in[3];
    const float* Wo   = (const float*)d_in[4];
    const float* bo   = (const float*)d_in[5];
    const float* g1   = (const float*)d_in[6];
    const float* b1   = (const float*)d_in[7];
    const float* g2   = (const float*)d_in[8];
    const float* b2   = (const float*)d_in[9];
    const float* W1   = (const float*)d_in[10];
    const float* bf1  = (const float*)d_in[11];
    const float* W2   = (const float*)d_in[12];
    const float* bf2  = (const float*)d_in[13];
    const float* gf   = (const float*)d_in[14];
    const float* bfp  = (const float*)d_in[15];
    const float* Wout = (const float*)d_in[16];
    const float* bfc  = (const float*)d_in[17];
    float* out = (float*)d_out;

    float *h, *t;
    cudaGetSymbolAddress((void**)&h, g_h);
    cudaGetSymbolAddress((void**)&t, g_t);
    __half *hf, *qf, *of, *ff, *tf;
    cudaGetSymbolAddress((void**)&hf, g_hf);
    cudaGetSymbolAddress((void**)&qf, g_qf);
    cudaGetSymbolAddress((void**)&of, g_of);
    cudaGetSymbolAddress((void**)&ff, g_ff);
    cudaGetSymbolAddress((void**)&tf, g_tf);
    __half *qkvTf, *woTf, *w1Tf, *w2Tf, *outTf;
    cudaGetSymbolAddress((void**)&qkvTf, g_qkvT_f);
    cudaGetSymbolAddress((void**)&woTf,  g_woT_f);
    cudaGetSymbolAddress((void**)&w1Tf,  g_w1T_f);
    cudaGetSymbolAddress((void**)&w2Tf,  g_w2T_f);
    cudaGetSymbolAddress((void**)&outTf, g_outT_f);

    cudaFuncSetAttribute(attn_f16, cudaFuncAttributeMaxDynamicSharedMemorySize, ATTF_SMEM);
    cudaFuncSetAttribute(gemm_f16<0,0>, cudaFuncAttributeMaxDynamicSharedMemorySize, F16_SMEM);
    cudaFuncSetAttribute(gemm_f16<0,1>, cudaFuncAttributeMaxDynamicSharedMemorySize, F16_SMEM);
    cudaFuncSetAttribute(gemm_f16<1,1>, cudaFuncAttributeMaxDynamicSharedMemorySize, F16_SMEM);

    wprep16_k<<<dim3(3*DD/32, DD/32, LL), 256>>>(Wqkv, qkvTf, DD, 3*DD);
    wprep16_k<<<dim3(DD/32,   DD/32, LL), 256>>>(Wo,   woTf,  DD, DD);
    wprep16_k<<<dim3(FF/32,   DD/32, LL), 256>>>(W1,   w1Tf,  DD, FF);
    wprep16_k<<<dim3(DD/32,   FF/32, LL), 256>>>(W2,   w2Tf,  FF, DD);
    wprep16_k<<<dim3(VV/32,   DD/32, 1 ), 256>>>(Wout, outTf, DD, VV);

    embed_k<<<ROWS, 128>>>(x, emb, pe, h, (uint32_t*)hf);

    for (int l = 0; l < LL; l++) {
        // QKV -> fp16 plane
        gemm_f16<0,1><<<dim3(32, 12), 256, F16_SMEM>>>(
            hf, qkvTf + (long)l * 3*DD*DD, nullptr,
            nullptr, (uint32_t*)qf, ROWS, 3*DD, DD);
        // attention (double-buffered KV) -> fp16 plane
        attn_f16<<<dim3(SS/128, HH, BB), 256, ATTF_SMEM>>>(qf, (uint32_t*)of);
        // Wo -> fp32 t (proven 128x128 kernel)
        gemm_f16<0,0><<<dim3(32, 4), 256, F16_SMEM>>>(
            of, woTf + (long)l * DD*DD, bo + l * DD,
            t, nullptr, ROWS, DD, DD);
        add_ln_k<<<ROWS, 128>>>(t, h, g1 + l * DD, b1 + l * DD, h, (uint32_t*)hf);
        // FF1 + relu -> fp16 plane
        gemm_f16<1,1><<<dim3(32, 16), 256, F16_SMEM>>>(
            hf, w1Tf + (long)l * FF*DD, bf1 + l * FF,
            nullptr, (uint32_t*)ff, ROWS, FF, DD);
        // FF2 -> fp32 t (proven 128x128 kernel)
        gemm_f16<0,0><<<dim3(32, 4), 256, F16_SMEM>>>(
            ff, w2Tf + (long)l * DD*FF, bf2 + l * DD,
            t, nullptr, ROWS, DD, FF);
        add_ln_k<<<ROWS, 128>>>(t, h, g2 + l * DD, b2 + l * DD, h, (uint32_t*)hf);
    }

    add_ln_k<<<ROWS, 128>>>(h, nullptr, gf, bfp, t, (uint32_t*)tf);
    gemm_f16<0,0><<<dim3(32, 250), 256, F16_SMEM>>>(
        tf, outTf, bfc, out, nullptr, ROWS, VV, DD);
}